// round 11
// baseline (speedup 1.0000x reference)
#include <cuda_runtime.h>
#include <cuda_fp16.h>
#include <math.h>
#include <stdint.h>

#define BQ    512
#define NC    131072
#define KD    192
#define H     256
#define NY    10
#define NNUM  8
#define NCAT  4
#define CARD  100

#define SPLITS 37
#define QT     128
#define CT     128
#define TTOT   (NC / CT)              /* 1024 tiles total */
#define PARTS  (SPLITS * 4)           /* 148 partial slots per query */

#define LOG2E 1.4426950408889634f

/* ---------------- global scratch ---------------- */
__device__ __half g_cz[(size_t)NC * KD];   /* z * log2e, f16 */
__device__ __half g_xz[(size_t)BQ * KD];
__device__ float  g_cn2[NC];
__device__ float  g_xn2[BQ];
__device__ __half g_yT[(size_t)16 * NC];
__device__ float  g_pl[(size_t)BQ * PARTS];
__device__ float  g_pacc[(size_t)BQ * PARTS * NY];
__device__ uint2  g_W2h[16 * 24 * 32];     /* f16 fragment-packed W2 */
__device__ float  g_U[NNUM * H];           /* folded numeric W1 */
__device__ float  g_b1p[H];                /* b1 + folded numeric bias */
__device__ __half g_T16[NCAT * CARD * H];  /* folded emb@W1 tables */

/* ---------------- helpers ---------------- */
__device__ __forceinline__ uint32_t smem_u32(const void* p) {
    uint32_t a;
    asm("{ .reg .u64 t; cvta.to.shared.u64 t, %1; cvt.u32.u64 %0, t; }" : "=r"(a) : "l"(p));
    return a;
}
__device__ __forceinline__ void mma_f16(float d[4], const uint32_t a[4], const uint32_t b[2]) {
    asm volatile("mma.sync.aligned.m16n8k16.row.col.f32.f16.f16.f32 "
        "{%0,%1,%2,%3}, {%4,%5,%6,%7}, {%8,%9}, {%0,%1,%2,%3};"
        : "+f"(d[0]), "+f"(d[1]), "+f"(d[2]), "+f"(d[3])
        : "r"(a[0]), "r"(a[1]), "r"(a[2]), "r"(a[3]), "r"(b[0]), "r"(b[1]));
}
__device__ __forceinline__ void ldsm_x4(uint32_t r[4], uint32_t addr) {
    asm volatile("ldmatrix.sync.aligned.m8n8.x4.shared.b16 {%0,%1,%2,%3}, [%4];"
        : "=r"(r[0]), "=r"(r[1]), "=r"(r[2]), "=r"(r[3]) : "r"(addr));
}
__device__ __forceinline__ uint32_t h2u(__half2 h) { return *reinterpret_cast<uint32_t*>(&h); }
__device__ __forceinline__ float rsqrt_ap(float x) {
    float r; asm("rsqrt.approx.f32 %0, %1;" : "=f"(r) : "f"(x)); return r;
}
__device__ __forceinline__ uint32_t cvt_h2(float hi, float lo) {
    uint32_t d; asm("cvt.rn.f16x2.f32 %0, %1, %2;" : "=r"(d) : "f"(hi), "f"(lo)); return d;
}
__device__ __forceinline__ uint32_t ex2_h2(uint32_t a) {
    uint32_t d; asm("ex2.approx.f16x2 %0, %1;" : "=r"(d) : "r"(a)); return d;
}
#define CP16(dst_u32, src_ptr) \
    asm volatile("cp.async.ca.shared.global [%0], [%1], 16;" :: "r"(dst_u32), "l"(src_ptr))
#define CP_COMMIT() asm volatile("cp.async.commit_group;" ::: "memory")
#define CP_WAIT1()  asm volatile("cp.async.wait_group 1;" ::: "memory")
#define CP_WAIT0()  asm volatile("cp.async.wait_group 0;" ::: "memory")

/* =========================================================================
 * Kernel P: prep.
 *   bid <  512 : y transpose
 *   512..559   : W2 fragment pack
 *   560..959   : T16 = emb @ W1catblock  (f16)
 *   bid == 960 : U = W_num-folded W1, b1p = b1 + b_num-folded W1
 * ========================================================================= */
__global__ __launch_bounds__(256) void prep_kernel(
    const float* __restrict__ cand_y,
    const float* __restrict__ W1, const float* __restrict__ W2,
    const float* __restrict__ W_num, const float* __restrict__ b_num,
    const float* __restrict__ emb, const float* __restrict__ b1)
{
    const int bid = blockIdx.x;
    const int tid = threadIdx.x;
    if (bid < 512) {
        const int c = bid * 256 + tid;
        #pragma unroll
        for (int d = 0; d < NY; d++)
            g_yT[(size_t)d * NC + c] = __float2half(cand_y[(size_t)c * NY + d]);
        g_yT[(size_t)10 * NC + c] = __float2half(1.0f);
        #pragma unroll
        for (int d = 11; d < 16; d++)
            g_yT[(size_t)d * NC + c] = __float2half(0.0f);
    } else if (bid < 560) {
        const int e = (bid - 512) * 256 + tid;
        if (e < 16 * 24 * 32) {
            const int lane = e & 31;
            const int lr = lane & 3, lq = lane >> 2;
            const int ks = e / 768, nb = (e >> 5) % 24;
            const int col = nb * 8 + lq;
            __half2 h0 = __floats2half2_rn(W2[(16 * ks + 2 * lr) * KD + col],
                                           W2[(16 * ks + 2 * lr + 1) * KD + col]);
            __half2 h1 = __floats2half2_rn(W2[(16 * ks + 8 + 2 * lr) * KD + col],
                                           W2[(16 * ks + 9 + 2 * lr) * KD + col]);
            g_W2h[e] = make_uint2(h2u(h0), h2u(h1));
        }
    } else if (bid < 960) {
        const int g = (bid - 560) * 256 + tid;    /* < 4*100*256 */
        const int j = g & 255;
        const int fc = g >> 8;                    /* f*100 + c */
        const int f = fc / CARD, c = fc % CARD;
        float s = 0.f;
        #pragma unroll
        for (int d = 0; d < 16; d++)
            s += emb[((size_t)(f * CARD + c)) * 16 + d] * W1[(128 + f * 16 + d) * H + j];
        g_T16[g] = __float2half(s);
    } else {
        const int j = tid;
        float bp = b1[j];
        #pragma unroll
        for (int f = 0; f < NNUM; f++) {
            float u = 0.f;
            #pragma unroll
            for (int d = 0; d < 16; d++) {
                u  += W_num[f * 16 + d] * W1[(f * 16 + d) * H + j];
                bp += b_num[f * 16 + d] * W1[(f * 16 + d) * H + j];
            }
            g_U[f * H + j] = u;
        }
        g_b1p[j] = bp;
    }
}

/* =========================================================================
 * Kernel 1: encode (folded GEMM1) + GEMM2, 64 rows/CTA.
 * smem: E32 f32[64][196] | Hs16 h[64][264] | Us f32[2048] | b1ps[256] | n2s[64]
 * ========================================================================= */
#define SE32 196
#define SH16 264
#define OFFE_HS  (64 * SE32 * 4)                  /* 50176 */
#define OFFE_U   (OFFE_HS + 64 * SH16 * 2)        /* 83968 */
#define OFFE_B1  (OFFE_U + NNUM * H * 4)          /* 92160 */
#define OFFE_N2  (OFFE_B1 + H * 4)                /* 93184 */
#define SMEM_ENC (OFFE_N2 + 64 * 4)               /* 93440 */

__global__ __launch_bounds__(256, 2) void encode_mlp_kernel(
    const float* __restrict__ c_num, const int* __restrict__ c_cat,
    const float* __restrict__ q_num, const int* __restrict__ q_cat,
    const float* __restrict__ W_num, const float* __restrict__ b_num,
    const float* __restrict__ emb, const float* __restrict__ b2)
{
    extern __shared__ char smraw[];
    float*  E32  = (float*)smraw;
    __half* Hs16 = (__half*)(smraw + OFFE_HS);
    float*  Us   = (float*)(smraw + OFFE_U);
    float*  b1ps = (float*)(smraw + OFFE_B1);
    float*  n2s  = (float*)(smraw + OFFE_N2);

    const int bid   = blockIdx.x;
    const int which = (bid >= NC / 64);
    const float* x_num = which ? q_num : c_num;
    const int*   x_cat = which ? q_cat : c_cat;
    __half* z  = which ? g_xz : g_cz;
    float*  n2 = which ? g_xn2 : g_cn2;
    const int row0 = (which ? (bid - NC / 64) : bid) * 64;

    const int tid  = threadIdx.x;
    const int lane = tid & 31;
    const int wid  = tid >> 5;

    if (tid < 64) n2s[tid] = 0.f;
    /* load folded weights to smem */
    #pragma unroll
    for (int e = tid; e < NNUM * H; e += 256) Us[e] = g_U[e];
    if (tid < H) b1ps[tid] = g_b1p[tid];

    /* E fill (f32, for residual + n2 only) */
    for (int e = tid; e < 64 * KD; e += 256) {
        const int r = e / KD, i = e % KD;
        const int row = row0 + r;
        float v;
        if (i < NNUM * 16) {
            const int f = i >> 4, d = i & 15;
            v = x_num[row * NNUM + f] * W_num[f * 16 + d] + b_num[f * 16 + d];
        } else {
            const int i2 = i - NNUM * 16;
            const int f = i2 >> 4, d = i2 & 15;
            const int idx = x_cat[row * NCAT + f];
            v = emb[((size_t)f * CARD + idx) * 16 + d];
        }
        E32[r * SE32 + i] = v;
    }
    __syncthreads();

    /* ---- H build: h[row][j] = relu(b1p[j] + sum_f x*U + sum_f T16) ---- */
    {
        const int hrow = tid >> 2;
        const int jc   = (tid & 3) * 64;
        float x8[8];
        #pragma unroll
        for (int f = 0; f < NNUM; f++) x8[f] = x_num[(row0 + hrow) * NNUM + f];
        const __half* tptr[4];
        #pragma unroll
        for (int f = 0; f < NCAT; f++) {
            const int idx = x_cat[(row0 + hrow) * NCAT + f];
            tptr[f] = g_T16 + ((size_t)(f * CARD + idx)) * H;
        }
        #pragma unroll
        for (int i = 0; i < 8; i++) {
            const int j = jc + i * 8;
            float acc[8];
            #pragma unroll
            for (int u = 0; u < 8; u++) acc[u] = b1ps[j + u];
            #pragma unroll
            for (int f = 0; f < NNUM; f++)
                #pragma unroll
                for (int u = 0; u < 8; u++)
                    acc[u] = fmaf(x8[f], Us[f * H + j + u], acc[u]);
            #pragma unroll
            for (int f = 0; f < NCAT; f++) {
                const uint4 tv = *(const uint4*)(tptr[f] + j);
                const __half2* hp = (const __half2*)&tv;
                #pragma unroll
                for (int u = 0; u < 4; u++) {
                    const float2 fv = __half22float2(hp[u]);
                    acc[2 * u]     += fv.x;
                    acc[2 * u + 1] += fv.y;
                }
            }
            __half2 ov[4];
            #pragma unroll
            for (int u = 0; u < 4; u++)
                ov[u] = __floats2half2_rn(fmaxf(acc[2 * u], 0.f),
                                          fmaxf(acc[2 * u + 1], 0.f));
            *(uint4*)(Hs16 + hrow * SH16 + j) = *(uint4*)ov;
        }
    }
    __syncthreads();

    const int lq = lane >> 2;
    const int lr = lane & 3;

    uint32_t hA[4];
    #pragma unroll
    for (int mt = 0; mt < 4; mt++)
        hA[mt] = smem_u32(Hs16 + (16 * mt + (lane & 15)) * SH16) + (lane >> 4) * 16;

    /* ---- GEMM2: z = (E + Hs @ W2 + b2) * log2e ---- */
    {
        const int nb0 = wid * 3;
        float d2[4][3][4];
        #pragma unroll
        for (int mt = 0; mt < 4; mt++)
            #pragma unroll
            for (int nt = 0; nt < 3; nt++)
                #pragma unroll
                for (int r = 0; r < 4; r++) d2[mt][nt][r] = 0.f;

        #pragma unroll 4
        for (int ks = 0; ks < H / 16; ks++) {
            uint32_t a[4][4];
            #pragma unroll
            for (int mt = 0; mt < 4; mt++) ldsm_x4(a[mt], hA[mt] + ks * 32);
            uint32_t b[3][2];
            #pragma unroll
            for (int nt = 0; nt < 3; nt++) {
                const uint2 w = g_W2h[(size_t)(ks * 24 + nb0 + nt) * 32 + lane];
                b[nt][0] = w.x; b[nt][1] = w.y;
            }
            #pragma unroll
            for (int mt = 0; mt < 4; mt++)
                #pragma unroll
                for (int nt = 0; nt < 3; nt++)
                    mma_f16(d2[mt][nt], a[mt], b[nt]);
        }

        #pragma unroll
        for (int mt = 0; mt < 4; mt++) {
            #pragma unroll
            for (int hh = 0; hh < 2; hh++) {
                const int r = 16 * mt + 8 * hh + lq;
                float rsum = 0.f;
                #pragma unroll
                for (int nt = 0; nt < 3; nt++) {
                    const int col = (nb0 + nt) * 8 + 2 * lr;
                    const float2 bb = *(const float2*)(b2 + col);
                    const float2 ef = *(const float2*)(E32 + r * SE32 + col);
                    const float vx = (d2[mt][nt][2 * hh]     + bb.x + ef.x) * LOG2E;
                    const float vy = (d2[mt][nt][2 * hh + 1] + bb.y + ef.y) * LOG2E;
                    const __half2 h2v = __floats2half2_rn(vx, vy);
                    const float2 vr = __half22float2(h2v);
                    rsum += vr.x * vr.x + vr.y * vr.y;
                    *(__half2*)(z + (size_t)(row0 + r) * KD + col) = h2v;
                }
                rsum += __shfl_xor_sync(0xffffffffu, rsum, 1);
                rsum += __shfl_xor_sync(0xffffffffu, rsum, 2);
                if (lr == 0) atomicAdd(n2s + r, rsum);
            }
        }
    }
    __syncthreads();
    if (tid < 64) n2[row0 + tid] = n2s[tid];
}

/* =========================================================================
 * Kernel 2: attention (unchanged from R8): 512 thr, 3-stage ring, cheap epi.
 * ========================================================================= */
#define SXH 200
#define SCH 200
#define SYH 136
#define CBYTES (128 * SCH * 2)
#define YBYTES (16 * SYH * 2)
#define OFF_X   0
#define OFF_C   (OFF_X + 128 * SXH * 2)
#define OFF_YT  (OFF_C + 3 * CBYTES)
#define OFF_CN  (OFF_YT + 3 * YBYTES)
#define SMEM_ATTN (OFF_CN + 3 * 128 * 4)

__global__ __launch_bounds__(512) void attn_kernel(void)
{
    extern __shared__ char smraw[];
    __half* X = (__half*)(smraw + OFF_X);
    __half* Cb[3]; __half* Yt[3]; float* Cn[3];
    #pragma unroll
    for (int i = 0; i < 3; i++) {
        Cb[i] = (__half*)(smraw + OFF_C + i * CBYTES);
        Yt[i] = (__half*)(smraw + OFF_YT + i * YBYTES);
        Cn[i] = (float*)(smraw + OFF_CN + i * 512);
    }

    const int tid   = threadIdx.x;
    const int lane  = tid & 31;
    const int wid   = tid >> 5;
    const int lq    = lane >> 2;
    const int lr    = lane & 3;
    const int qg    = wid >> 2;
    const int cg    = wid & 3;
    const int split = blockIdx.x;
    const int q0    = blockIdx.y * QT;

    const int t0 = (split * TTOT) / SPLITS;
    const int t1 = ((split + 1) * TTOT) / SPLITS;

    for (int e = tid * 8; e < 128 * KD; e += 512 * 8) {
        const int q = e / KD, k = e % KD;
        *(float4*)(X + q * SXH + k) = *(const float4*)(g_xz + (size_t)(q0 + q) * KD + k);
    }

    float xn2v[4];
    #pragma unroll
    for (int mt = 0; mt < 2; mt++)
        #pragma unroll
        for (int hh = 0; hh < 2; hh++)
            xn2v[2 * mt + hh] = g_xn2[q0 + 32 * qg + 16 * mt + 8 * hh + lq];

    uint32_t xA[2];
    #pragma unroll
    for (int mt = 0; mt < 2; mt++)
        xA[mt] = smem_u32(X + (32 * qg + 16 * mt + (lane & 15)) * SXH) + (lane >> 4) * 16;

    const int bg = lane >> 3;
    uint32_t cBrow[3][2];
    #pragma unroll
    for (int st = 0; st < 3; st++)
        #pragma unroll
        for (int p = 0; p < 2; p++) {
            const int row = 32 * cg + 16 * p + ((bg >> 1) << 3) + (lane & 7);
            cBrow[st][p] = smem_u32(Cb[st] + row * SCH) + (bg & 1) * 16;
        }

    auto issue = [&](int t, int st) {
        const int cb = t * CT;
        __half* Cd = Cb[st];
        const __half* src = g_cz + (size_t)cb * KD;
        #pragma unroll 3
        for (int e = tid; e < 128 * 24; e += 512) {
            const int c = e / 24, seg = e % 24;
            CP16(smem_u32(Cd + c * SCH + seg * 8), src + (size_t)c * KD + seg * 8);
        }
        if (tid < 256) {
            const int d = tid >> 4, seg = tid & 15;
            CP16(smem_u32(Yt[st] + d * SYH + seg * 8), g_yT + (size_t)d * NC + cb + seg * 8);
        }
        if (tid < 32) CP16(smem_u32(Cn[st] + tid * 4), g_cn2 + cb + tid * 4);
        CP_COMMIT();
    };

    issue(t0, 0);
    issue(t0 + 1, 1);

    float d2acc[2][2][4];
    #pragma unroll
    for (int mt = 0; mt < 2; mt++)
        #pragma unroll
        for (int n = 0; n < 2; n++)
            #pragma unroll
            for (int r = 0; r < 4; r++) d2acc[mt][n][r] = 0.f;

    int st = 0;
    for (int t = t0; t < t1; t++) {
        if (t + 1 < t1) { CP_WAIT1(); } else { CP_WAIT0(); }
        __syncthreads();
        const int stN = (st + 2 >= 3) ? st - 1 : st + 2;
        if (t + 2 < t1) issue(t + 2, stN);

        float d1[2][4][4];
        #pragma unroll
        for (int mt = 0; mt < 2; mt++)
            #pragma unroll
            for (int nt = 0; nt < 4; nt++)
                #pragma unroll
                for (int r = 0; r < 4; r++) d1[mt][nt][r] = 0.f;

        #pragma unroll
        for (int ks = 0; ks < KD / 16; ks++) {
            uint32_t a[2][4];
            #pragma unroll
            for (int mt = 0; mt < 2; mt++) ldsm_x4(a[mt], xA[mt] + ks * 32);
            #pragma unroll
            for (int p = 0; p < 2; p++) {
                uint32_t bw[4];
                ldsm_x4(bw, cBrow[st][p] + ks * 32);
                uint32_t b0[2] = {bw[0], bw[1]};
                uint32_t b1r[2] = {bw[2], bw[3]};
                #pragma unroll
                for (int mt = 0; mt < 2; mt++) {
                    mma_f16(d1[mt][2 * p],     a[mt], b0);
                    mma_f16(d1[mt][2 * p + 1], a[mt], b1r);
                }
            }
        }

        uint32_t plo[2][4], phi[2][4];
        const float* CnS = Cn[st];
        #pragma unroll
        for (int nt = 0; nt < 4; nt++) {
            const int col = 32 * cg + 8 * nt + 2 * lr;
            const float2 cn = *(const float2*)(CnS + col);
            #pragma unroll
            for (int mt = 0; mt < 2; mt++) {
                const float xlo = xn2v[2 * mt];
                const float xhi = xn2v[2 * mt + 1];
                const float dd0 = fmaxf(fmaf(-2.f, d1[mt][nt][0], xlo + cn.x), 1e-20f);
                const float dd1 = fmaxf(fmaf(-2.f, d1[mt][nt][1], xlo + cn.y), 1e-20f);
                const float dd2 = fmaxf(fmaf(-2.f, d1[mt][nt][2], xhi + cn.x), 1e-20f);
                const float dd3 = fmaxf(fmaf(-2.f, d1[mt][nt][3], xhi + cn.y), 1e-20f);
                const float nd0 = dd0 * (-rsqrt_ap(dd0));
                const float nd1 = dd1 * (-rsqrt_ap(dd1));
                const float nd2 = dd2 * (-rsqrt_ap(dd2));
                const float nd3 = dd3 * (-rsqrt_ap(dd3));
                plo[mt][nt] = ex2_h2(cvt_h2(nd1, nd0));
                phi[mt][nt] = ex2_h2(cvt_h2(nd3, nd2));
            }
        }

        const __half* YtS = Yt[st];
        #pragma unroll
        for (int ks2 = 0; ks2 < 2; ks2++) {
            #pragma unroll
            for (int mt = 0; mt < 2; mt++) {
                uint32_t a[4];
                a[0] = plo[mt][2 * ks2];
                a[1] = phi[mt][2 * ks2];
                a[2] = plo[mt][2 * ks2 + 1];
                a[3] = phi[mt][2 * ks2 + 1];
                #pragma unroll
                for (int ntY = 0; ntY < 2; ntY++) {
                    uint32_t b[2];
                    b[0] = *(const uint32_t*)(YtS + (8 * ntY + lq) * SYH + 32 * cg + 16 * ks2 + 2 * lr);
                    b[1] = *(const uint32_t*)(YtS + (8 * ntY + lq) * SYH + 32 * cg + 16 * ks2 + 8 + 2 * lr);
                    mma_f16(d2acc[mt][ntY], a, b);
                }
            }
        }
        st = (st + 1 == 3) ? 0 : st + 1;
    }

    #pragma unroll
    for (int mt = 0; mt < 2; mt++) {
        #pragma unroll
        for (int ntY = 0; ntY < 2; ntY++) {
            #pragma unroll
            for (int hh = 0; hh < 2; hh++) {
                #pragma unroll
                for (int pr = 0; pr < 2; pr++) {
                    const int d = 8 * ntY + 2 * lr + pr;
                    const int q = q0 + 32 * qg + 16 * mt + 8 * hh + lq;
                    const float v = d2acc[mt][ntY][2 * hh + pr];
                    const size_t slot = ((size_t)q * SPLITS + split) * 4 + cg;
                    if (d < NY)
                        g_pacc[slot * NY + d] = v;
                    else if (d == 10)
                        g_pl[slot] = v;
                }
            }
        }
    }
}

/* =========================================================================
 * Kernel 3: sum 148 partials per query, normalize.
 * ========================================================================= */
__global__ __launch_bounds__(32) void reduce_kernel(float* __restrict__ out)
{
    const int q = blockIdx.x;
    const int lane = threadIdx.x;

    float l = 0.f;
    float a[NY];
    #pragma unroll
    for (int d = 0; d < NY; d++) a[d] = 0.f;

    for (int s = lane; s < PARTS; s += 32) {
        const size_t i = (size_t)q * PARTS + s;
        l += g_pl[i];
        #pragma unroll
        for (int d = 0; d < NY; d++) a[d] += g_pacc[i * NY + d];
    }
    #pragma unroll
    for (int m = 16; m >= 1; m >>= 1) {
        l += __shfl_xor_sync(0xffffffffu, l, m);
        #pragma unroll
        for (int d = 0; d < NY; d++) a[d] += __shfl_xor_sync(0xffffffffu, a[d], m);
    }

    if (lane == 0) {
        const float invL = 1.f / l;
        #pragma unroll
        for (int d = 0; d < NY; d++) out[q * NY + d] = a[d] * invL;
    }
}

/* ========================================================================= */
extern "C" void kernel_launch(void* const* d_in, const int* in_sizes, int n_in,
                              void* d_out, int out_size)
{
    const float* x_num      = (const float*)d_in[0];
    const int*   x_cat      = (const int*)  d_in[1];
    const float* cand_x_num = (const float*)d_in[2];
    const int*   cand_x_cat = (const int*)  d_in[3];
    const float* cand_y     = (const float*)d_in[4];
    const float* W_num      = (const float*)d_in[5];
    const float* b_num      = (const float*)d_in[6];
    const float* emb        = (const float*)d_in[7];
    const float* W1         = (const float*)d_in[8];
    const float* b1         = (const float*)d_in[9];
    const float* W2         = (const float*)d_in[10];
    const float* b2         = (const float*)d_in[11];
    float* out = (float*)d_out;

    cudaFuncSetAttribute(encode_mlp_kernel,
                         cudaFuncAttributeMaxDynamicSharedMemorySize, SMEM_ENC);
    cudaFuncSetAttribute(attn_kernel,
                         cudaFuncAttributeMaxDynamicSharedMemorySize, SMEM_ATTN);

    prep_kernel<<<961, 256>>>(cand_y, W1, W2, W_num, b_num, emb, b1);

    encode_mlp_kernel<<<NC / 64 + BQ / 64, 256, SMEM_ENC>>>(
        cand_x_num, cand_x_cat, x_num, x_cat, W_num, b_num, emb, b2);

    dim3 ag(SPLITS, BQ / QT);
    attn_kernel<<<ag, 512, SMEM_ATTN>>>();

    reduce_kernel<<<BQ, 32>>>(out);
}

// round 15
// speedup vs baseline: 1.6289x; 1.6289x over previous
#include <cuda_runtime.h>
#include <cuda_fp16.h>
#include <math.h>
#include <stdint.h>

#define BQ    512
#define NC    131072
#define KD    192
#define H     256
#define NY    10
#define NNUM  8
#define NCAT  4
#define CARD  100

#define SPLITS 37
#define QT     128
#define CT     128
#define TTOT   (NC / CT)              /* 1024 tiles total */
#define PARTS  (SPLITS * 4)           /* 148 partial slots per query */

#define LOG2E 1.4426950408889634f

/* ---------------- global scratch ---------------- */
__device__ __half g_cz[(size_t)NC * KD];   /* z * log2e, f16 */
__device__ __half g_xz[(size_t)BQ * KD];
__device__ float  g_cn2[NC];               /* ||z*log2e||^2 */
__device__ float  g_xn2[BQ];
__device__ __half g_yT[(size_t)16 * NC];
__device__ float  g_pl[(size_t)BQ * PARTS];
__device__ float  g_pacc[(size_t)BQ * PARTS * NY];
__device__ uint2  g_W1h[12 * 32 * 32];
__device__ uint2  g_W2h[16 * 24 * 32];

/* ---------------- helpers ---------------- */
__device__ __forceinline__ uint32_t smem_u32(const void* p) {
    uint32_t a;
    asm("{ .reg .u64 t; cvta.to.shared.u64 t, %1; cvt.u32.u64 %0, t; }" : "=r"(a) : "l"(p));
    return a;
}
__device__ __forceinline__ void mma_f16(float d[4], const uint32_t a[4], const uint32_t b[2]) {
    asm volatile("mma.sync.aligned.m16n8k16.row.col.f32.f16.f16.f32 "
        "{%0,%1,%2,%3}, {%4,%5,%6,%7}, {%8,%9}, {%0,%1,%2,%3};"
        : "+f"(d[0]), "+f"(d[1]), "+f"(d[2]), "+f"(d[3])
        : "r"(a[0]), "r"(a[1]), "r"(a[2]), "r"(a[3]), "r"(b[0]), "r"(b[1]));
}
__device__ __forceinline__ void ldsm_x4(uint32_t r[4], uint32_t addr) {
    asm volatile("ldmatrix.sync.aligned.m8n8.x4.shared.b16 {%0,%1,%2,%3}, [%4];"
        : "=r"(r[0]), "=r"(r[1]), "=r"(r[2]), "=r"(r[3]) : "r"(addr));
}
__device__ __forceinline__ uint32_t h2u(__half2 h) { return *reinterpret_cast<uint32_t*>(&h); }
__device__ __forceinline__ float rsqrt_ap(float x) {
    float r; asm("rsqrt.approx.f32 %0, %1;" : "=f"(r) : "f"(x)); return r;
}
__device__ __forceinline__ uint32_t cvt_h2(float hi, float lo) {
    uint32_t d; asm("cvt.rn.f16x2.f32 %0, %1, %2;" : "=r"(d) : "f"(hi), "f"(lo)); return d;
}
__device__ __forceinline__ uint32_t ex2_h2(uint32_t a) {
    uint32_t d; asm("ex2.approx.f16x2 %0, %1;" : "=r"(d) : "r"(a)); return d;
}
#define CP16(dst_u32, src_ptr) \
    asm volatile("cp.async.ca.shared.global [%0], [%1], 16;" :: "r"(dst_u32), "l"(src_ptr))
#define CP_COMMIT() asm volatile("cp.async.commit_group;" ::: "memory")
#define CP_WAIT1()  asm volatile("cp.async.wait_group 1;" ::: "memory")
#define CP_WAIT0()  asm volatile("cp.async.wait_group 0;" ::: "memory")

/* =========================================================================
 * Kernel P: prep — y transpose via smem staging (CTAs 0..511) +
 *                  W pack (CTAs 512..607)
 * ========================================================================= */
__global__ __launch_bounds__(256) void prep_kernel(
    const float* __restrict__ cand_y,
    const float* __restrict__ W1, const float* __restrict__ W2)
{
    __shared__ float sy[256 * NY];
    const int bid = blockIdx.x;
    const int tid = threadIdx.x;
    if (bid < 512) {
        const int c0 = bid * 256;
        /* coalesced stage-in: 2560 contiguous floats */
        for (int i = tid; i < 256 * NY; i += 256)
            sy[i] = cand_y[(size_t)c0 * NY + i];
        __syncthreads();
        const int c = c0 + tid;
        #pragma unroll
        for (int d = 0; d < NY; d++)
            g_yT[(size_t)d * NC + c] = __float2half(sy[tid * NY + d]);
        g_yT[(size_t)10 * NC + c] = __float2half(1.0f);
        #pragma unroll
        for (int d = 11; d < 16; d++)
            g_yT[(size_t)d * NC + c] = __float2half(0.0f);
    } else {
        const int g = (bid - 512) * 256 + tid;
        const int lane = g & 31;
        const int lr = lane & 3, lq = lane >> 2;
        if (g < 12 * 32 * 32) {
            const int ks = g >> 10, nb = (g >> 5) & 31;
            const int col = nb * 8 + lq;
            __half2 h0 = __floats2half2_rn(W1[(16 * ks + 2 * lr) * H + col],
                                           W1[(16 * ks + 2 * lr + 1) * H + col]);
            __half2 h1 = __floats2half2_rn(W1[(16 * ks + 8 + 2 * lr) * H + col],
                                           W1[(16 * ks + 9 + 2 * lr) * H + col]);
            g_W1h[g] = make_uint2(h2u(h0), h2u(h1));
        } else {
            const int e = g - 12 * 32 * 32;
            const int ks = e / 768, rem = e % 768;
            const int nb = rem >> 5;
            const int col = nb * 8 + lq;
            __half2 h0 = __floats2half2_rn(W2[(16 * ks + 2 * lr) * KD + col],
                                           W2[(16 * ks + 2 * lr + 1) * KD + col]);
            __half2 h1 = __floats2half2_rn(W2[(16 * ks + 8 + 2 * lr) * KD + col],
                                           W2[(16 * ks + 9 + 2 * lr) * KD + col]);
            g_W2h[e] = make_uint2(h2u(h0), h2u(h1));
        }
    }
}

/* =========================================================================
 * Kernel 1: encode + residual MLP, 64 rows/CTA, merged cand+query grid.
 * smem: E16 h[64][200] | Hs16 h[64][264] | n2s[64]
 * ========================================================================= */
#define SE16 200
#define SH16 264
#define OFFE_HS  (64 * SE16 * 2)
#define OFFE_N2  (OFFE_HS + 64 * SH16 * 2)
#define SMEM_ENC (OFFE_N2 + 64 * 4)

__global__ __launch_bounds__(256, 2) void encode_mlp_kernel(
    const float* __restrict__ c_num, const int* __restrict__ c_cat,
    const float* __restrict__ q_num, const int* __restrict__ q_cat,
    const float* __restrict__ W_num, const float* __restrict__ b_num,
    const float* __restrict__ emb,
    const float* __restrict__ b1, const float* __restrict__ b2)
{
    extern __shared__ char smraw[];
    __half* E16  = (__half*)smraw;
    __half* Hs16 = (__half*)(smraw + OFFE_HS);
    float*  n2s  = (float*)(smraw + OFFE_N2);

    const int bid   = blockIdx.x;
    const int which = (bid >= NC / 64);
    const float* x_num = which ? q_num : c_num;
    const int*   x_cat = which ? q_cat : c_cat;
    __half* z  = which ? g_xz : g_cz;
    float*  n2 = which ? g_xn2 : g_cn2;
    const int row0 = (which ? (bid - NC / 64) : bid) * 64;

    const int tid  = threadIdx.x;
    const int lane = tid & 31;
    const int wid  = tid >> 5;

    if (tid < 64) n2s[tid] = 0.f;

    for (int e = tid; e < 64 * KD; e += 256) {
        const int r = e / KD, i = e % KD;
        const int row = row0 + r;
        float v;
        if (i < NNUM * 16) {
            const int f = i >> 4, d = i & 15;
            v = x_num[row * NNUM + f] * W_num[f * 16 + d] + b_num[f * 16 + d];
        } else {
            const int i2 = i - NNUM * 16;
            const int f = i2 >> 4, d = i2 & 15;
            const int idx = x_cat[row * NCAT + f];
            v = emb[((size_t)f * CARD + idx) * 16 + d];
        }
        E16[r * SE16 + i] = __float2half(v);
    }
    __syncthreads();

    const int lq = lane >> 2;
    const int lr = lane & 3;

    uint32_t eA[4], hA[4];
    #pragma unroll
    for (int mt = 0; mt < 4; mt++) {
        eA[mt] = smem_u32(E16 + (16 * mt + (lane & 15)) * SE16) + (lane >> 4) * 16;
        hA[mt] = smem_u32(Hs16 + (16 * mt + (lane & 15)) * SH16) + (lane >> 4) * 16;
    }

    /* ---- GEMM1: relu(E @ W1 + b1) -> Hs16 ---- */
    {
        const int nb0 = wid * 4;
        float d1[4][4][4];
        #pragma unroll
        for (int mt = 0; mt < 4; mt++)
            #pragma unroll
            for (int nt = 0; nt < 4; nt++)
                #pragma unroll
                for (int r = 0; r < 4; r++) d1[mt][nt][r] = 0.f;

        #pragma unroll 4
        for (int ks = 0; ks < KD / 16; ks++) {
            uint32_t a[4][4];
            #pragma unroll
            for (int mt = 0; mt < 4; mt++) ldsm_x4(a[mt], eA[mt] + ks * 32);
            uint32_t b[4][2];
            #pragma unroll
            for (int nt = 0; nt < 4; nt++) {
                const uint2 w = g_W1h[(size_t)(ks * 32 + nb0 + nt) * 32 + lane];
                b[nt][0] = w.x; b[nt][1] = w.y;
            }
            #pragma unroll
            for (int mt = 0; mt < 4; mt++)
                #pragma unroll
                for (int nt = 0; nt < 4; nt++)
                    mma_f16(d1[mt][nt], a[mt], b[nt]);
        }

        #pragma unroll
        for (int nt = 0; nt < 4; nt++) {
            const int col = (nb0 + nt) * 8 + 2 * lr;
            const float2 bb = *(const float2*)(b1 + col);
            #pragma unroll
            for (int mt = 0; mt < 4; mt++) {
                const int rA = 16 * mt + lq;
                __half2 h0 = __floats2half2_rn(fmaxf(d1[mt][nt][0] + bb.x, 0.f),
                                               fmaxf(d1[mt][nt][1] + bb.y, 0.f));
                __half2 h1 = __floats2half2_rn(fmaxf(d1[mt][nt][2] + bb.x, 0.f),
                                               fmaxf(d1[mt][nt][3] + bb.y, 0.f));
                *(__half2*)(Hs16 + rA * SH16 + col)       = h0;
                *(__half2*)(Hs16 + (rA + 8) * SH16 + col) = h1;
            }
        }
    }
    __syncthreads();

    /* ---- GEMM2: z = (E + Hs @ W2 + b2) * log2e ---- */
    {
        const int nb0 = wid * 3;
        float d2[4][3][4];
        #pragma unroll
        for (int mt = 0; mt < 4; mt++)
            #pragma unroll
            for (int nt = 0; nt < 3; nt++)
                #pragma unroll
                for (int r = 0; r < 4; r++) d2[mt][nt][r] = 0.f;

        #pragma unroll 4
        for (int ks = 0; ks < H / 16; ks++) {
            uint32_t a[4][4];
            #pragma unroll
            for (int mt = 0; mt < 4; mt++) ldsm_x4(a[mt], hA[mt] + ks * 32);
            uint32_t b[3][2];
            #pragma unroll
            for (int nt = 0; nt < 3; nt++) {
                const uint2 w = g_W2h[(size_t)(ks * 24 + nb0 + nt) * 32 + lane];
                b[nt][0] = w.x; b[nt][1] = w.y;
            }
            #pragma unroll
            for (int mt = 0; mt < 4; mt++)
                #pragma unroll
                for (int nt = 0; nt < 3; nt++)
                    mma_f16(d2[mt][nt], a[mt], b[nt]);
        }

        #pragma unroll
        for (int mt = 0; mt < 4; mt++) {
            #pragma unroll
            for (int hh = 0; hh < 2; hh++) {
                const int r = 16 * mt + 8 * hh + lq;
                float rsum = 0.f;
                #pragma unroll
                for (int nt = 0; nt < 3; nt++) {
                    const int col = (nb0 + nt) * 8 + 2 * lr;
                    const float2 bb = *(const float2*)(b2 + col);
                    const float2 ef = __half22float2(*(const __half2*)(E16 + r * SE16 + col));
                    const float vx = (d2[mt][nt][2 * hh]     + bb.x + ef.x) * LOG2E;
                    const float vy = (d2[mt][nt][2 * hh + 1] + bb.y + ef.y) * LOG2E;
                    const __half2 h2v = __floats2half2_rn(vx, vy);
                    const float2 vr = __half22float2(h2v);
                    rsum += vr.x * vr.x + vr.y * vr.y;
                    *(__half2*)(z + (size_t)(row0 + r) * KD + col) = h2v;
                }
                rsum += __shfl_xor_sync(0xffffffffu, rsum, 1);
                rsum += __shfl_xor_sync(0xffffffffu, rsum, 2);
                if (lr == 0) atomicAdd(n2s + r, rsum);
            }
        }
    }
    __syncthreads();
    if (tid < 64) n2[row0 + tid] = n2s[tid];
}

/* =========================================================================
 * Kernel 2: attention, 512 threads, 3-stage cp.async ring, cheap epilogue.
 * p = ex2(-d2*rsqrt(d2)) with pre-scaled z (d2 already * log2e^2).
 * ========================================================================= */
#define SXH 200
#define SCH 200
#define SYH 136
#define CBYTES (128 * SCH * 2)
#define YBYTES (16 * SYH * 2)
#define OFF_X   0
#define OFF_C   (OFF_X + 128 * SXH * 2)
#define OFF_YT  (OFF_C + 3 * CBYTES)
#define OFF_CN  (OFF_YT + 3 * YBYTES)
#define SMEM_ATTN (OFF_CN + 3 * 128 * 4)

__global__ __launch_bounds__(512) void attn_kernel(void)
{
    extern __shared__ char smraw[];
    __half* X = (__half*)(smraw + OFF_X);
    __half* Cb[3]; __half* Yt[3]; float* Cn[3];
    #pragma unroll
    for (int i = 0; i < 3; i++) {
        Cb[i] = (__half*)(smraw + OFF_C + i * CBYTES);
        Yt[i] = (__half*)(smraw + OFF_YT + i * YBYTES);
        Cn[i] = (float*)(smraw + OFF_CN + i * 512);
    }

    const int tid   = threadIdx.x;
    const int lane  = tid & 31;
    const int wid   = tid >> 5;
    const int lq    = lane >> 2;
    const int lr    = lane & 3;
    const int qg    = wid >> 2;
    const int cg    = wid & 3;
    const int split = blockIdx.x;
    const int q0    = blockIdx.y * QT;

    const int t0 = (split * TTOT) / SPLITS;
    const int t1 = ((split + 1) * TTOT) / SPLITS;

    for (int e = tid * 8; e < 128 * KD; e += 512 * 8) {
        const int q = e / KD, k = e % KD;
        *(float4*)(X + q * SXH + k) = *(const float4*)(g_xz + (size_t)(q0 + q) * KD + k);
    }

    float xn2v[4];
    #pragma unroll
    for (int mt = 0; mt < 2; mt++)
        #pragma unroll
        for (int hh = 0; hh < 2; hh++)
            xn2v[2 * mt + hh] = g_xn2[q0 + 32 * qg + 16 * mt + 8 * hh + lq];

    uint32_t xA[2];
    #pragma unroll
    for (int mt = 0; mt < 2; mt++)
        xA[mt] = smem_u32(X + (32 * qg + 16 * mt + (lane & 15)) * SXH) + (lane >> 4) * 16;

    const int bg = lane >> 3;
    uint32_t cBrow[3][2];
    #pragma unroll
    for (int st = 0; st < 3; st++)
        #pragma unroll
        for (int p = 0; p < 2; p++) {
            const int row = 32 * cg + 16 * p + ((bg >> 1) << 3) + (lane & 7);
            cBrow[st][p] = smem_u32(Cb[st] + row * SCH) + (bg & 1) * 16;
        }

    auto issue = [&](int t, int st) {
        const int cb = t * CT;
        __half* Cd = Cb[st];
        const __half* src = g_cz + (size_t)cb * KD;
        #pragma unroll 3
        for (int e = tid; e < 128 * 24; e += 512) {
            const int c = e / 24, seg = e % 24;
            CP16(smem_u32(Cd + c * SCH + seg * 8), src + (size_t)c * KD + seg * 8);
        }
        if (tid < 256) {
            const int d = tid >> 4, seg = tid & 15;
            CP16(smem_u32(Yt[st] + d * SYH + seg * 8), g_yT + (size_t)d * NC + cb + seg * 8);
        }
        if (tid < 32) CP16(smem_u32(Cn[st] + tid * 4), g_cn2 + cb + tid * 4);
        CP_COMMIT();
    };

    issue(t0, 0);
    issue(t0 + 1, 1);

    float d2acc[2][2][4];
    #pragma unroll
    for (int mt = 0; mt < 2; mt++)
        #pragma unroll
        for (int n = 0; n < 2; n++)
            #pragma unroll
            for (int r = 0; r < 4; r++) d2acc[mt][n][r] = 0.f;

    int st = 0;
    for (int t = t0; t < t1; t++) {
        if (t + 1 < t1) { CP_WAIT1(); } else { CP_WAIT0(); }
        __syncthreads();
        const int stN = (st + 2 >= 3) ? st - 1 : st + 2;
        if (t + 2 < t1) issue(t + 2, stN);

        float d1[2][4][4];
        #pragma unroll
        for (int mt = 0; mt < 2; mt++)
            #pragma unroll
            for (int nt = 0; nt < 4; nt++)
                #pragma unroll
                for (int r = 0; r < 4; r++) d1[mt][nt][r] = 0.f;

        #pragma unroll
        for (int ks = 0; ks < KD / 16; ks++) {
            uint32_t a[2][4];
            #pragma unroll
            for (int mt = 0; mt < 2; mt++) ldsm_x4(a[mt], xA[mt] + ks * 32);
            #pragma unroll
            for (int p = 0; p < 2; p++) {
                uint32_t bw[4];
                ldsm_x4(bw, cBrow[st][p] + ks * 32);
                uint32_t b0[2] = {bw[0], bw[1]};
                uint32_t b1r[2] = {bw[2], bw[3]};
                #pragma unroll
                for (int mt = 0; mt < 2; mt++) {
                    mma_f16(d1[mt][2 * p],     a[mt], b0);
                    mma_f16(d1[mt][2 * p + 1], a[mt], b1r);
                }
            }
        }

        uint32_t plo[2][4], phi[2][4];
        const float* CnS = Cn[st];
        #pragma unroll
        for (int nt = 0; nt < 4; nt++) {
            const int col = 32 * cg + 8 * nt + 2 * lr;
            const float2 cn = *(const float2*)(CnS + col);
            #pragma unroll
            for (int mt = 0; mt < 2; mt++) {
                const float xlo = xn2v[2 * mt];
                const float xhi = xn2v[2 * mt + 1];
                const float dd0 = fmaxf(fmaf(-2.f, d1[mt][nt][0], xlo + cn.x), 1e-20f);
                const float dd1 = fmaxf(fmaf(-2.f, d1[mt][nt][1], xlo + cn.y), 1e-20f);
                const float dd2 = fmaxf(fmaf(-2.f, d1[mt][nt][2], xhi + cn.x), 1e-20f);
                const float dd3 = fmaxf(fmaf(-2.f, d1[mt][nt][3], xhi + cn.y), 1e-20f);
                const float nd0 = dd0 * (-rsqrt_ap(dd0));
                const float nd1 = dd1 * (-rsqrt_ap(dd1));
                const float nd2 = dd2 * (-rsqrt_ap(dd2));
                const float nd3 = dd3 * (-rsqrt_ap(dd3));
                plo[mt][nt] = ex2_h2(cvt_h2(nd1, nd0));
                phi[mt][nt] = ex2_h2(cvt_h2(nd3, nd2));
            }
        }

        const __half* YtS = Yt[st];
        #pragma unroll
        for (int ks2 = 0; ks2 < 2; ks2++) {
            #pragma unroll
            for (int mt = 0; mt < 2; mt++) {
                uint32_t a[4];
                a[0] = plo[mt][2 * ks2];
                a[1] = phi[mt][2 * ks2];
                a[2] = plo[mt][2 * ks2 + 1];
                a[3] = phi[mt][2 * ks2 + 1];
                #pragma unroll
                for (int ntY = 0; ntY < 2; ntY++) {
                    uint32_t b[2];
                    b[0] = *(const uint32_t*)(YtS + (8 * ntY + lq) * SYH + 32 * cg + 16 * ks2 + 2 * lr);
                    b[1] = *(const uint32_t*)(YtS + (8 * ntY + lq) * SYH + 32 * cg + 16 * ks2 + 8 + 2 * lr);
                    mma_f16(d2acc[mt][ntY], a, b);
                }
            }
        }
        st = (st + 1 == 3) ? 0 : st + 1;
    }

    /* write partials: slot = (q*SPLITS+split)*4 + cg */
    #pragma unroll
    for (int mt = 0; mt < 2; mt++) {
        #pragma unroll
        for (int ntY = 0; ntY < 2; ntY++) {
            #pragma unroll
            for (int hh = 0; hh < 2; hh++) {
                #pragma unroll
                for (int pr = 0; pr < 2; pr++) {
                    const int d = 8 * ntY + 2 * lr + pr;
                    const int q = q0 + 32 * qg + 16 * mt + 8 * hh + lq;
                    const float v = d2acc[mt][ntY][2 * hh + pr];
                    const size_t slot = ((size_t)q * SPLITS + split) * 4 + cg;
                    if (d < NY)
                        g_pacc[slot * NY + d] = v;
                    else if (d == 10)
                        g_pl[slot] = v;
                }
            }
        }
    }
}

/* =========================================================================
 * Kernel 3: sum 148 partials per query, normalize. 8 queries per block.
 * ========================================================================= */
__global__ __launch_bounds__(256) void reduce_kernel(float* __restrict__ out)
{
    const int w = threadIdx.x >> 5;
    const int q = blockIdx.x * 8 + w;
    const int lane = threadIdx.x & 31;

    float l = 0.f;
    float a[NY];
    #pragma unroll
    for (int d = 0; d < NY; d++) a[d] = 0.f;

    for (int s = lane; s < PARTS; s += 32) {
        const size_t i = (size_t)q * PARTS + s;
        l += g_pl[i];
        #pragma unroll
        for (int d = 0; d < NY; d++) a[d] += g_pacc[i * NY + d];
    }
    #pragma unroll
    for (int m = 16; m >= 1; m >>= 1) {
        l += __shfl_xor_sync(0xffffffffu, l, m);
        #pragma unroll
        for (int d = 0; d < NY; d++) a[d] += __shfl_xor_sync(0xffffffffu, a[d], m);
    }

    if (lane == 0) {
        const float invL = 1.f / l;
        #pragma unroll
        for (int d = 0; d < NY; d++) out[q * NY + d] = a[d] * invL;
    }
}

/* ========================================================================= */
extern "C" void kernel_launch(void* const* d_in, const int* in_sizes, int n_in,
                              void* d_out, int out_size)
{
    const float* x_num      = (const float*)d_in[0];
    const int*   x_cat      = (const int*)  d_in[1];
    const float* cand_x_num = (const float*)d_in[2];
    const int*   cand_x_cat = (const int*)  d_in[3];
    const float* cand_y     = (const float*)d_in[4];
    const float* W_num      = (const float*)d_in[5];
    const float* b_num      = (const float*)d_in[6];
    const float* emb        = (const float*)d_in[7];
    const float* W1         = (const float*)d_in[8];
    const float* b1         = (const float*)d_in[9];
    const float* W2         = (const float*)d_in[10];
    const float* b2         = (const float*)d_in[11];
    float* out = (float*)d_out;

    cudaFuncSetAttribute(encode_mlp_kernel,
                         cudaFuncAttributeMaxDynamicSharedMemorySize, SMEM_ENC);
    cudaFuncSetAttribute(attn_kernel,
                         cudaFuncAttributeMaxDynamicSharedMemorySize, SMEM_ATTN);

    prep_kernel<<<608, 256>>>(cand_y, W1, W2);

    encode_mlp_kernel<<<NC / 64 + BQ / 64, 256, SMEM_ENC>>>(
        cand_x_num, cand_x_cat, x_num, x_cat, W_num, b_num, emb, b1, b2);

    dim3 ag(SPLITS, BQ / QT);
    attn_kernel<<<ag, 512, SMEM_ATTN>>>();

    reduce_kernel<<<BQ / 8, 256>>>(out);
}

// round 17
// speedup vs baseline: 1.6369x; 1.0049x over previous
#include <cuda_runtime.h>
#include <cuda_fp16.h>
#include <math.h>
#include <stdint.h>

#define BQ    512
#define NC    131072
#define KD    192
#define H     256
#define NY    10
#define NNUM  8
#define NCAT  4
#define CARD  100

#define SPLITS 37
#define QT     128
#define CT     128
#define TTOT   (NC / CT)              /* 1024 tiles total */
#define PARTS  (SPLITS * 4)           /* 148 partial slots per query */

#define LOG2E 1.4426950408889634f

/* ---------------- global scratch ---------------- */
__device__ __half g_cz[(size_t)NC * KD];   /* z * log2e, f16 */
__device__ __half g_xz[(size_t)BQ * KD];
__device__ float  g_cn2[NC];               /* ||z*log2e||^2 */
__device__ float  g_xn2[BQ];
__device__ __half g_yT[(size_t)16 * NC];
__device__ float  g_pl[(size_t)BQ * PARTS];
__device__ float  g_pacc[(size_t)BQ * PARTS * NY];
__device__ uint2  g_W1h[12 * 32 * 32];
__device__ uint2  g_W2h[16 * 24 * 32];

/* ---------------- helpers ---------------- */
__device__ __forceinline__ uint32_t smem_u32(const void* p) {
    uint32_t a;
    asm("{ .reg .u64 t; cvta.to.shared.u64 t, %1; cvt.u32.u64 %0, t; }" : "=r"(a) : "l"(p));
    return a;
}
__device__ __forceinline__ void mma_f16(float d[4], const uint32_t a[4], const uint32_t b[2]) {
    asm volatile("mma.sync.aligned.m16n8k16.row.col.f32.f16.f16.f32 "
        "{%0,%1,%2,%3}, {%4,%5,%6,%7}, {%8,%9}, {%0,%1,%2,%3};"
        : "+f"(d[0]), "+f"(d[1]), "+f"(d[2]), "+f"(d[3])
        : "r"(a[0]), "r"(a[1]), "r"(a[2]), "r"(a[3]), "r"(b[0]), "r"(b[1]));
}
/* f16 accumulator variant: D,C packed half2 pairs (row lq / lq+8) */
__device__ __forceinline__ void mma_f16a(uint32_t d[2], const uint32_t a[4], const uint32_t b[2]) {
    asm volatile("mma.sync.aligned.m16n8k16.row.col.f16.f16.f16.f16 "
        "{%0,%1}, {%2,%3,%4,%5}, {%6,%7}, {%0,%1};"
        : "+r"(d[0]), "+r"(d[1])
        : "r"(a[0]), "r"(a[1]), "r"(a[2]), "r"(a[3]), "r"(b[0]), "r"(b[1]));
}
__device__ __forceinline__ void ldsm_x4(uint32_t r[4], uint32_t addr) {
    asm volatile("ldmatrix.sync.aligned.m8n8.x4.shared.b16 {%0,%1,%2,%3}, [%4];"
        : "=r"(r[0]), "=r"(r[1]), "=r"(r[2]), "=r"(r[3]) : "r"(addr));
}
__device__ __forceinline__ uint32_t h2u(__half2 h) { return *reinterpret_cast<uint32_t*>(&h); }
__device__ __forceinline__ __half2 u2h(uint32_t u) { return *reinterpret_cast<__half2*>(&u); }
__device__ __forceinline__ float rsqrt_ap(float x) {
    float r; asm("rsqrt.approx.f32 %0, %1;" : "=f"(r) : "f"(x)); return r;
}
__device__ __forceinline__ uint32_t cvt_h2(float hi, float lo) {
    uint32_t d; asm("cvt.rn.f16x2.f32 %0, %1, %2;" : "=r"(d) : "f"(hi), "f"(lo)); return d;
}
__device__ __forceinline__ uint32_t ex2_h2(uint32_t a) {
    uint32_t d; asm("ex2.approx.f16x2 %0, %1;" : "=r"(d) : "r"(a)); return d;
}
#define CP16(dst_u32, src_ptr) \
    asm volatile("cp.async.ca.shared.global [%0], [%1], 16;" :: "r"(dst_u32), "l"(src_ptr))
#define CP_COMMIT() asm volatile("cp.async.commit_group;" ::: "memory")
#define CP_WAIT1()  asm volatile("cp.async.wait_group 1;" ::: "memory")
#define CP_WAIT0()  asm volatile("cp.async.wait_group 0;" ::: "memory")

/* =========================================================================
 * Kernel P: prep — W1/W2 fragment pack only (96 CTAs).
 * ========================================================================= */
__global__ __launch_bounds__(256) void prep_kernel(
    const float* __restrict__ W1, const float* __restrict__ W2)
{
    const int g = blockIdx.x * 256 + threadIdx.x;
    const int lane = g & 31;
    const int lr = lane & 3, lq = lane >> 2;
    if (g < 12 * 32 * 32) {
        const int ks = g >> 10, nb = (g >> 5) & 31;
        const int col = nb * 8 + lq;
        __half2 h0 = __floats2half2_rn(W1[(16 * ks + 2 * lr) * H + col],
                                       W1[(16 * ks + 2 * lr + 1) * H + col]);
        __half2 h1 = __floats2half2_rn(W1[(16 * ks + 8 + 2 * lr) * H + col],
                                       W1[(16 * ks + 9 + 2 * lr) * H + col]);
        g_W1h[g] = make_uint2(h2u(h0), h2u(h1));
    } else {
        const int e = g - 12 * 32 * 32;
        const int ks = e / 768, rem = e % 768;
        const int nb = rem >> 5;
        const int col = nb * 8 + lq;
        __half2 h0 = __floats2half2_rn(W2[(16 * ks + 2 * lr) * KD + col],
                                       W2[(16 * ks + 2 * lr + 1) * KD + col]);
        __half2 h1 = __floats2half2_rn(W2[(16 * ks + 8 + 2 * lr) * KD + col],
                                       W2[(16 * ks + 9 + 2 * lr) * KD + col]);
        g_W2h[e] = make_uint2(h2u(h0), h2u(h1));
    }
}

/* =========================================================================
 * Kernel 1: encode + residual MLP (f16 accumulators) + y-transpose CTAs.
 *   bid < 2056 : encode 64 rows
 *   bid >= 2056: y transpose (512 CTAs, overlapped)
 * smem: E16 h[64][200] | Hs16 h[64][264] | n2s[64]
 * ========================================================================= */
#define SE16 200
#define SH16 264
#define OFFE_HS  (64 * SE16 * 2)
#define OFFE_N2  (OFFE_HS + 64 * SH16 * 2)
#define SMEM_ENC (OFFE_N2 + 64 * 4)
#define ENC_CTAS (NC / 64 + BQ / 64)          /* 2056 */

__global__ __launch_bounds__(256, 2) void encode_mlp_kernel(
    const float* __restrict__ c_num, const int* __restrict__ c_cat,
    const float* __restrict__ q_num, const int* __restrict__ q_cat,
    const float* __restrict__ W_num, const float* __restrict__ b_num,
    const float* __restrict__ emb,
    const float* __restrict__ b1, const float* __restrict__ b2,
    const float* __restrict__ cand_y)
{
    extern __shared__ char smraw[];
    const int bid = blockIdx.x;
    const int tid = threadIdx.x;

    /* ---- y-transpose CTAs (independent; overlap encode) ---- */
    if (bid >= ENC_CTAS) {
        float* sy = (float*)smraw;
        const int c0 = (bid - ENC_CTAS) * 256;
        for (int i = tid; i < 256 * NY; i += 256)
            sy[i] = cand_y[(size_t)c0 * NY + i];
        __syncthreads();
        const int c = c0 + tid;
        #pragma unroll
        for (int d = 0; d < NY; d++)
            g_yT[(size_t)d * NC + c] = __float2half(sy[tid * NY + d]);
        g_yT[(size_t)10 * NC + c] = __float2half(1.0f);
        #pragma unroll
        for (int d = 11; d < 16; d++)
            g_yT[(size_t)d * NC + c] = __float2half(0.0f);
        return;
    }

    __half* E16  = (__half*)smraw;
    __half* Hs16 = (__half*)(smraw + OFFE_HS);
    float*  n2s  = (float*)(smraw + OFFE_N2);

    const int which = (bid >= NC / 64);
    const float* x_num = which ? q_num : c_num;
    const int*   x_cat = which ? q_cat : c_cat;
    __half* z  = which ? g_xz : g_cz;
    float*  n2 = which ? g_xn2 : g_cn2;
    const int row0 = (which ? (bid - NC / 64) : bid) * 64;

    const int lane = tid & 31;
    const int wid  = tid >> 5;

    if (tid < 64) n2s[tid] = 0.f;

    for (int e = tid; e < 64 * KD; e += 256) {
        const int r = e / KD, i = e % KD;
        const int row = row0 + r;
        float v;
        if (i < NNUM * 16) {
            const int f = i >> 4, d = i & 15;
            v = x_num[row * NNUM + f] * W_num[f * 16 + d] + b_num[f * 16 + d];
        } else {
            const int i2 = i - NNUM * 16;
            const int f = i2 >> 4, d = i2 & 15;
            const int idx = x_cat[row * NCAT + f];
            v = emb[((size_t)f * CARD + idx) * 16 + d];
        }
        E16[r * SE16 + i] = __float2half(v);
    }
    __syncthreads();

    const int lq = lane >> 2;
    const int lr = lane & 3;

    uint32_t eA[4], hA[4];
    #pragma unroll
    for (int mt = 0; mt < 4; mt++) {
        eA[mt] = smem_u32(E16 + (16 * mt + (lane & 15)) * SE16) + (lane >> 4) * 16;
        hA[mt] = smem_u32(Hs16 + (16 * mt + (lane & 15)) * SH16) + (lane >> 4) * 16;
    }

    const __half2 zero2 = __float2half2_rn(0.f);

    /* ---- GEMM1 (f16 acc): relu(E @ W1 + b1) -> Hs16 ---- */
    {
        const int nb0 = wid * 4;
        uint32_t d1[4][4][2];
        #pragma unroll
        for (int mt = 0; mt < 4; mt++)
            #pragma unroll
            for (int nt = 0; nt < 4; nt++) { d1[mt][nt][0] = 0u; d1[mt][nt][1] = 0u; }

        #pragma unroll 4
        for (int ks = 0; ks < KD / 16; ks++) {
            uint32_t a[4][4];
            #pragma unroll
            for (int mt = 0; mt < 4; mt++) ldsm_x4(a[mt], eA[mt] + ks * 32);
            uint32_t b[4][2];
            #pragma unroll
            for (int nt = 0; nt < 4; nt++) {
                const uint2 w = g_W1h[(size_t)(ks * 32 + nb0 + nt) * 32 + lane];
                b[nt][0] = w.x; b[nt][1] = w.y;
            }
            #pragma unroll
            for (int mt = 0; mt < 4; mt++)
                #pragma unroll
                for (int nt = 0; nt < 4; nt++)
                    mma_f16a(d1[mt][nt], a[mt], b[nt]);
        }

        #pragma unroll
        for (int nt = 0; nt < 4; nt++) {
            const int col = (nb0 + nt) * 8 + 2 * lr;
            const float2 bbf = *(const float2*)(b1 + col);
            const __half2 bb2 = __floats2half2_rn(bbf.x, bbf.y);
            #pragma unroll
            for (int mt = 0; mt < 4; mt++) {
                const int rA = 16 * mt + lq;
                const __half2 h0 = __hmax2(__hadd2(u2h(d1[mt][nt][0]), bb2), zero2);
                const __half2 h1 = __hmax2(__hadd2(u2h(d1[mt][nt][1]), bb2), zero2);
                *(__half2*)(Hs16 + rA * SH16 + col)       = h0;
                *(__half2*)(Hs16 + (rA + 8) * SH16 + col) = h1;
            }
        }
    }
    __syncthreads();

    /* ---- GEMM2 (f16 acc): z = (E + Hs @ W2 + b2) * log2e ---- */
    {
        const int nb0 = wid * 3;
        const __half2 l2e2 = __float2half2_rn(LOG2E);
        uint32_t d2[4][3][2];
        #pragma unroll
        for (int mt = 0; mt < 4; mt++)
            #pragma unroll
            for (int nt = 0; nt < 3; nt++) { d2[mt][nt][0] = 0u; d2[mt][nt][1] = 0u; }

        #pragma unroll 4
        for (int ks = 0; ks < H / 16; ks++) {
            uint32_t a[4][4];
            #pragma unroll
            for (int mt = 0; mt < 4; mt++) ldsm_x4(a[mt], hA[mt] + ks * 32);
            uint32_t b[3][2];
            #pragma unroll
            for (int nt = 0; nt < 3; nt++) {
                const uint2 w = g_W2h[(size_t)(ks * 24 + nb0 + nt) * 32 + lane];
                b[nt][0] = w.x; b[nt][1] = w.y;
            }
            #pragma unroll
            for (int mt = 0; mt < 4; mt++)
                #pragma unroll
                for (int nt = 0; nt < 3; nt++)
                    mma_f16a(d2[mt][nt], a[mt], b[nt]);
        }

        #pragma unroll
        for (int mt = 0; mt < 4; mt++) {
            #pragma unroll
            for (int hh = 0; hh < 2; hh++) {
                const int r = 16 * mt + 8 * hh + lq;
                float rsum = 0.f;
                #pragma unroll
                for (int nt = 0; nt < 3; nt++) {
                    const int col = (nb0 + nt) * 8 + 2 * lr;
                    const float2 bbf = *(const float2*)(b2 + col);
                    const __half2 bb2 = __floats2half2_rn(bbf.x, bbf.y);
                    const __half2 ef = *(const __half2*)(E16 + r * SE16 + col);
                    const __half2 v = __hmul2(
                        __hadd2(__hadd2(u2h(d2[mt][nt][hh]), bb2), ef), l2e2);
                    const float2 vr = __half22float2(v);
                    rsum += vr.x * vr.x + vr.y * vr.y;
                    *(__half2*)(z + (size_t)(row0 + r) * KD + col) = v;
                }
                rsum += __shfl_xor_sync(0xffffffffu, rsum, 1);
                rsum += __shfl_xor_sync(0xffffffffu, rsum, 2);
                if (lr == 0) atomicAdd(n2s + r, rsum);
            }
        }
    }
    __syncthreads();
    if (tid < 64) n2[row0 + tid] = n2s[tid];
}

/* =========================================================================
 * Kernel 2: attention — byte-identical to the 274.6us R8 version.
 * ========================================================================= */
#define SXH 200
#define SCH 200
#define SYH 136
#define CBYTES (128 * SCH * 2)
#define YBYTES (16 * SYH * 2)
#define OFF_X   0
#define OFF_C   (OFF_X + 128 * SXH * 2)
#define OFF_YT  (OFF_C + 3 * CBYTES)
#define OFF_CN  (OFF_YT + 3 * YBYTES)
#define SMEM_ATTN (OFF_CN + 3 * 128 * 4)

__global__ __launch_bounds__(512) void attn_kernel(void)
{
    extern __shared__ char smraw[];
    __half* X = (__half*)(smraw + OFF_X);
    __half* Cb[3]; __half* Yt[3]; float* Cn[3];
    #pragma unroll
    for (int i = 0; i < 3; i++) {
        Cb[i] = (__half*)(smraw + OFF_C + i * CBYTES);
        Yt[i] = (__half*)(smraw + OFF_YT + i * YBYTES);
        Cn[i] = (float*)(smraw + OFF_CN + i * 512);
    }

    const int tid   = threadIdx.x;
    const int lane  = tid & 31;
    const int wid   = tid >> 5;
    const int lq    = lane >> 2;
    const int lr    = lane & 3;
    const int qg    = wid >> 2;
    const int cg    = wid & 3;
    const int split = blockIdx.x;
    const int q0    = blockIdx.y * QT;

    const int t0 = (split * TTOT) / SPLITS;
    const int t1 = ((split + 1) * TTOT) / SPLITS;

    for (int e = tid * 8; e < 128 * KD; e += 512 * 8) {
        const int q = e / KD, k = e % KD;
        *(float4*)(X + q * SXH + k) = *(const float4*)(g_xz + (size_t)(q0 + q) * KD + k);
    }

    float xn2v[4];
    #pragma unroll
    for (int mt = 0; mt < 2; mt++)
        #pragma unroll
        for (int hh = 0; hh < 2; hh++)
            xn2v[2 * mt + hh] = g_xn2[q0 + 32 * qg + 16 * mt + 8 * hh + lq];

    uint32_t xA[2];
    #pragma unroll
    for (int mt = 0; mt < 2; mt++)
        xA[mt] = smem_u32(X + (32 * qg + 16 * mt + (lane & 15)) * SXH) + (lane >> 4) * 16;

    const int bg = lane >> 3;
    uint32_t cBrow[3][2];
    #pragma unroll
    for (int st = 0; st < 3; st++)
        #pragma unroll
        for (int p = 0; p < 2; p++) {
            const int row = 32 * cg + 16 * p + ((bg >> 1) << 3) + (lane & 7);
            cBrow[st][p] = smem_u32(Cb[st] + row * SCH) + (bg & 1) * 16;
        }

    auto issue = [&](int t, int st) {
        const int cb = t * CT;
        __half* Cd = Cb[st];
        const __half* src = g_cz + (size_t)cb * KD;
        #pragma unroll 3
        for (int e = tid; e < 128 * 24; e += 512) {
            const int c = e / 24, seg = e % 24;
            CP16(smem_u32(Cd + c * SCH + seg * 8), src + (size_t)c * KD + seg * 8);
        }
        if (tid < 256) {
            const int d = tid >> 4, seg = tid & 15;
            CP16(smem_u32(Yt[st] + d * SYH + seg * 8), g_yT + (size_t)d * NC + cb + seg * 8);
        }
        if (tid < 32) CP16(smem_u32(Cn[st] + tid * 4), g_cn2 + cb + tid * 4);
        CP_COMMIT();
    };

    issue(t0, 0);
    issue(t0 + 1, 1);

    float d2acc[2][2][4];
    #pragma unroll
    for (int mt = 0; mt < 2; mt++)
        #pragma unroll
        for (int n = 0; n < 2; n++)
            #pragma unroll
            for (int r = 0; r < 4; r++) d2acc[mt][n][r] = 0.f;

    int st = 0;
    for (int t = t0; t < t1; t++) {
        if (t + 1 < t1) { CP_WAIT1(); } else { CP_WAIT0(); }
        __syncthreads();
        const int stN = (st + 2 >= 3) ? st - 1 : st + 2;
        if (t + 2 < t1) issue(t + 2, stN);

        float d1[2][4][4];
        #pragma unroll
        for (int mt = 0; mt < 2; mt++)
            #pragma unroll
            for (int nt = 0; nt < 4; nt++)
                #pragma unroll
                for (int r = 0; r < 4; r++) d1[mt][nt][r] = 0.f;

        #pragma unroll
        for (int ks = 0; ks < KD / 16; ks++) {
            uint32_t a[2][4];
            #pragma unroll
            for (int mt = 0; mt < 2; mt++) ldsm_x4(a[mt], xA[mt] + ks * 32);
            #pragma unroll
            for (int p = 0; p < 2; p++) {
                uint32_t bw[4];
                ldsm_x4(bw, cBrow[st][p] + ks * 32);
                uint32_t b0[2] = {bw[0], bw[1]};
                uint32_t b1r[2] = {bw[2], bw[3]};
                #pragma unroll
                for (int mt = 0; mt < 2; mt++) {
                    mma_f16(d1[mt][2 * p],     a[mt], b0);
                    mma_f16(d1[mt][2 * p + 1], a[mt], b1r);
                }
            }
        }

        uint32_t plo[2][4], phi[2][4];
        const float* CnS = Cn[st];
        #pragma unroll
        for (int nt = 0; nt < 4; nt++) {
            const int col = 32 * cg + 8 * nt + 2 * lr;
            const float2 cn = *(const float2*)(CnS + col);
            #pragma unroll
            for (int mt = 0; mt < 2; mt++) {
                const float xlo = xn2v[2 * mt];
                const float xhi = xn2v[2 * mt + 1];
                const float dd0 = fmaxf(fmaf(-2.f, d1[mt][nt][0], xlo + cn.x), 1e-20f);
                const float dd1 = fmaxf(fmaf(-2.f, d1[mt][nt][1], xlo + cn.y), 1e-20f);
                const float dd2 = fmaxf(fmaf(-2.f, d1[mt][nt][2], xhi + cn.x), 1e-20f);
                const float dd3 = fmaxf(fmaf(-2.f, d1[mt][nt][3], xhi + cn.y), 1e-20f);
                const float nd0 = dd0 * (-rsqrt_ap(dd0));
                const float nd1 = dd1 * (-rsqrt_ap(dd1));
                const float nd2 = dd2 * (-rsqrt_ap(dd2));
                const float nd3 = dd3 * (-rsqrt_ap(dd3));
                plo[mt][nt] = ex2_h2(cvt_h2(nd1, nd0));
                phi[mt][nt] = ex2_h2(cvt_h2(nd3, nd2));
            }
        }

        const __half* YtS = Yt[st];
        #pragma unroll
        for (int ks2 = 0; ks2 < 2; ks2++) {
            #pragma unroll
            for (int mt = 0; mt < 2; mt++) {
                uint32_t a[4];
                a[0] = plo[mt][2 * ks2];
                a[1] = phi[mt][2 * ks2];
                a[2] = plo[mt][2 * ks2 + 1];
                a[3] = phi[mt][2 * ks2 + 1];
                #pragma unroll
                for (int ntY = 0; ntY < 2; ntY++) {
                    uint32_t b[2];
                    b[0] = *(const uint32_t*)(YtS + (8 * ntY + lq) * SYH + 32 * cg + 16 * ks2 + 2 * lr);
                    b[1] = *(const uint32_t*)(YtS + (8 * ntY + lq) * SYH + 32 * cg + 16 * ks2 + 8 + 2 * lr);
                    mma_f16(d2acc[mt][ntY], a, b);
                }
            }
        }
        st = (st + 1 == 3) ? 0 : st + 1;
    }

    /* write partials: slot = (q*SPLITS+split)*4 + cg */
    #pragma unroll
    for (int mt = 0; mt < 2; mt++) {
        #pragma unroll
        for (int ntY = 0; ntY < 2; ntY++) {
            #pragma unroll
            for (int hh = 0; hh < 2; hh++) {
                #pragma unroll
                for (int pr = 0; pr < 2; pr++) {
                    const int d = 8 * ntY + 2 * lr + pr;
                    const int q = q0 + 32 * qg + 16 * mt + 8 * hh + lq;
                    const float v = d2acc[mt][ntY][2 * hh + pr];
                    const size_t slot = ((size_t)q * SPLITS + split) * 4 + cg;
                    if (d < NY)
                        g_pacc[slot * NY + d] = v;
                    else if (d == 10)
                        g_pl[slot] = v;
                }
            }
        }
    }
}

/* =========================================================================
 * Kernel 3: sum 148 partials per query, normalize (R8-measured form).
 * ========================================================================= */
__global__ __launch_bounds__(32) void reduce_kernel(float* __restrict__ out)
{
    const int q = blockIdx.x;
    const int lane = threadIdx.x;

    float l = 0.f;
    float a[NY];
    #pragma unroll
    for (int d = 0; d < NY; d++) a[d] = 0.f;

    for (int s = lane; s < PARTS; s += 32) {
        const size_t i = (size_t)q * PARTS + s;
        l += g_pl[i];
        #pragma unroll
        for (int d = 0; d < NY; d++) a[d] += g_pacc[i * NY + d];
    }
    #pragma unroll
    for (int m = 16; m >= 1; m >>= 1) {
        l += __shfl_xor_sync(0xffffffffu, l, m);
        #pragma unroll
        for (int d = 0; d < NY; d++) a[d] += __shfl_xor_sync(0xffffffffu, a[d], m);
    }

    if (lane == 0) {
        const float invL = 1.f / l;
        #pragma unroll
        for (int d = 0; d < NY; d++) out[q * NY + d] = a[d] * invL;
    }
}

/* ========================================================================= */
extern "C" void kernel_launch(void* const* d_in, const int* in_sizes, int n_in,
                              void* d_out, int out_size)
{
    const float* x_num      = (const float*)d_in[0];
    const int*   x_cat      = (const int*)  d_in[1];
    const float* cand_x_num = (const float*)d_in[2];
    const int*   cand_x_cat = (const int*)  d_in[3];
    const float* cand_y     = (const float*)d_in[4];
    const float* W_num      = (const float*)d_in[5];
    const float* b_num      = (const float*)d_in[6];
    const float* emb        = (const float*)d_in[7];
    const float* W1         = (const float*)d_in[8];
    const float* b1         = (const float*)d_in[9];
    const float* W2         = (const float*)d_in[10];
    const float* b2         = (const float*)d_in[11];
    float* out = (float*)d_out;

    cudaFuncSetAttribute(encode_mlp_kernel,
                         cudaFuncAttributeMaxDynamicSharedMemorySize, SMEM_ENC);
    cudaFuncSetAttribute(attn_kernel,
                         cudaFuncAttributeMaxDynamicSharedMemorySize, SMEM_ATTN);

    prep_kernel<<<96, 256>>>(W1, W2);

    /* encode (2056 CTAs) + y-transpose (512 CTAs) in one grid */
    encode_mlp_kernel<<<ENC_CTAS + 512, 256, SMEM_ENC>>>(
        cand_x_num, cand_x_cat, x_num, x_cat, W_num, b_num, emb, b1, b2, cand_y);

    dim3 ag(SPLITS, BQ / QT);
    attn_kernel<<<ag, 512, SMEM_ATTN>>>();

    reduce_kernel<<<BQ, 32>>>(out);
}